// round 8
// baseline (speedup 1.0000x reference)
#include <cuda_runtime.h>

#define Tt 2048
#define Bb 512
#define Cc 8
#define Hh 20
#define GRP 4
#define RING 8

typedef unsigned long long u64;

__device__ __forceinline__ u64 pack2(float a, float b) {
    u64 r; asm("mov.b64 %0, {%1, %2};" : "=l"(r) : "f"(a), "f"(b)); return r;
}
__device__ __forceinline__ void unpack2(u64 v, float &a, float &b) {
    asm("mov.b64 {%0, %1}, %2;" : "=f"(a), "=f"(b) : "l"(v));
}
// packed dual-FMA: d.x += a.x*b.x ; d.y += a.y*b.y
__device__ __forceinline__ void ffma2(u64 &d, u64 a, u64 b) {
    asm("fma.rn.f32x2 %0, %1, %2, %0;" : "+l"(d) : "l"(a), "l"(b));
}
__device__ __forceinline__ float hadd2(u64 v) {
    float a, b; unpack2(v, a, b); return a + b;
}
__device__ __forceinline__ float tanhfast(float x) {
    float y; asm("tanh.approx.f32 %0, %1;" : "=f"(y) : "f"(x)); return y;
}

// 4 warps per batch (block = 1 batch): layer pair {half0: gates i,f; half1:
// gates g,o}. Gate exchange via bar.sync(1+layer, 64) each step; both warps
// replicate the cell update so h stays in-register. L1 pair -> L2 pair
// handoff through a depth-8 ring with bar.sync(0,128) every 4 steps (R3
// pattern). 3-4 blocks/SM => 3-4 warps/SMSP hide the serial chains that
// capped the 2-warp design at issue=40%.
__global__ void __launch_bounds__(128, 4) lstm2_kernel(
    const float* __restrict__ x,
    const float* __restrict__ Wih0, const float* __restrict__ Whh0,
    const float* __restrict__ bih0, const float* __restrict__ bhh0,
    const float* __restrict__ Wih1, const float* __restrict__ Whh1,
    const float* __restrict__ bih1, const float* __restrict__ bhh1,
    float* __restrict__ out)
{
    __shared__ __align__(16) float  ring[RING][24];       // h1 broadcast (L1-half0 writes)
    __shared__ __align__(16) float2 gex[2][2][2][32];     // [layer][slot][half][lane]
    __shared__ __align__(16) float  h1b[24];              // L1-half1 private h1 copy
    __shared__ __align__(16) float  h2b[2][24];           // L2 per-half private h2 copies

    const int tid   = threadIdx.x;
    const int w     = tid >> 5;
    const int lane  = tid & 31;
    // role flip by block parity so each SMSP hosts a mix of L1/L2 warps
    const int lw    = w ^ ((blockIdx.x & 1) << 1);
    const int layer = lw >> 1;
    const int half  = lw & 1;
    const int batch = blockIdx.x;
    const int pbar  = 1 + layer;          // per-pair barrier id (64 threads)

    // activation constants: gate A is tanh for half1 (gate g), else sigmoid.
    // act(x) = s*tanh(k*x) + d ;  sigmoid: k=.5,s=.5,d=.5 ; tanh: k=1,s=1,d=0
    const float kA = half ? 1.0f : 0.5f;
    const float sA = half ? 1.0f : 0.5f;
    const float dA = half ? 0.0f : 0.5f;

    if (layer == 0) {
        // ---------------- layer 1 pair ----------------
        u64 wxA[4], wxB[4], whA[10], whB[10], bA = 0, bB = 0;
        if (lane < Hh) {
            const int rowA = (2 * half)     * Hh + lane;   // gate order i,f,g,o
            const int rowB = (2 * half + 1) * Hh + lane;
            const float* rxA = Wih0 + rowA * Cc;
            const float* rxB = Wih0 + rowB * Cc;
            #pragma unroll
            for (int kp = 0; kp < 4; kp++) {
                wxA[kp] = pack2(rxA[2*kp], rxA[2*kp+1]);
                wxB[kp] = pack2(rxB[2*kp], rxB[2*kp+1]);
            }
            const float* rhA = Whh0 + rowA * Hh;
            const float* rhB = Whh0 + rowB * Hh;
            #pragma unroll
            for (int kp = 0; kp < 10; kp++) {
                whA[kp] = pack2(rhA[2*kp], rhA[2*kp+1]);
                whB[kp] = pack2(rhB[2*kp], rhB[2*kp+1]);
            }
            bA = pack2(bih0[rowA] + bhh0[rowA], 0.f);
            bB = pack2(bih0[rowB] + bhh0[rowB], 0.f);
        }
        // x prefetch pipeline, depth 2 (uniform LDG.128 pairs, broadcast)
        const ulonglong2* xb = ((const ulonglong2*)x) + (size_t)batch * 2;
        ulonglong2 x0a = xb[0],    x0b = xb[1];
        ulonglong2 x1a = xb[1024], x1b = xb[1025];
        u64 hp[10];
        #pragma unroll
        for (int kp = 0; kp < 10; kp++) hp[kp] = 0ull;
        float c1 = 0.f;

        #pragma unroll 1
        for (int p = 0; p < Tt / GRP; p++) {
            #pragma unroll
            for (int s = 0; s < GRP; s++) {
                const int t = p * GRP + s;
                u64 xv0 = x0a.x, xv1 = x0a.y, xv2 = x0b.x, xv3 = x0b.y;
                x0a = x1a; x0b = x1b;
                if (t + 2 < Tt) {
                    const ulonglong2* xq = xb + (size_t)(t + 2) * 1024;
                    x1a = xq[0]; x1b = xq[1];
                }
                u64 aA = bA, aB = bB;
                ffma2(aA, wxA[0], xv0); ffma2(aB, wxB[0], xv0);
                ffma2(aA, wxA[1], xv1); ffma2(aB, wxB[1], xv1);
                ffma2(aA, wxA[2], xv2); ffma2(aB, wxB[2], xv2);
                ffma2(aA, wxA[3], xv3); ffma2(aB, wxB[3], xv3);
                #pragma unroll
                for (int kp = 0; kp < 10; kp++) {
                    u64 v = hp[kp];
                    ffma2(aA, whA[kp], v); ffma2(aB, whB[kp], v);
                }
                // gate A: sigmoid (half0:i) / tanh (half1:g); gate B: sigmoid (f / o)
                float vA = fmaf(tanhfast(kA * hadd2(aA)), sA, dA);
                float vB = fmaf(tanhfast(0.5f * hadd2(aB)), 0.5f, 0.5f);
                gex[0][t & 1][half][lane] = make_float2(vA, vB);
                asm volatile("bar.sync %0, 64;" :: "r"(pbar) : "memory");
                float2 oth = gex[0][t & 1][half ^ 1][lane];
                float i_ = half ? oth.x : vA;
                float f_ = half ? oth.y : vB;
                float g_ = half ? vA : oth.x;
                float o_ = half ? vB : oth.y;
                c1 = fmaf(f_, c1, i_ * g_);
                float h1 = o_ * tanhfast(c1);
                float* hdst = half ? &h1b[0] : &ring[t & (RING - 1)][0];
                if (lane < Hh) hdst[lane] = h1;
                __syncwarp();
                const u64* rp = (const u64*)hdst;
                #pragma unroll
                for (int kp = 0; kp < 10; kp++) hp[kp] = rp[kp];
            }
            asm volatile("bar.sync 0, 128;" ::: "memory");
        }
    } else {
        // ---------------- layer 2 pair (one group behind) ----------------
        u64 w1A[10], w1B[10], w2A[10], w2B[10], bA = 0, bB = 0;
        if (lane < Hh) {
            const int rowA = (2 * half)     * Hh + lane;
            const int rowB = (2 * half + 1) * Hh + lane;
            const float* r1A = Wih1 + rowA * Hh;
            const float* r1B = Wih1 + rowB * Hh;
            const float* r2A = Whh1 + rowA * Hh;
            const float* r2B = Whh1 + rowB * Hh;
            #pragma unroll
            for (int kp = 0; kp < 10; kp++) {
                w1A[kp] = pack2(r1A[2*kp], r1A[2*kp+1]);
                w1B[kp] = pack2(r1B[2*kp], r1B[2*kp+1]);
                w2A[kp] = pack2(r2A[2*kp], r2A[2*kp+1]);
                w2B[kp] = pack2(r2B[2*kp], r2B[2*kp+1]);
            }
            bA = pack2(bih1[rowA] + bhh1[rowA], 0.f);
            bB = pack2(bih1[rowB] + bhh1[rowB], 0.f);
        }
        u64 h2p[10];
        #pragma unroll
        for (int kp = 0; kp < 10; kp++) h2p[kp] = 0ull;
        float c2 = 0.f;
        float* outp = out + (size_t)batch * Hh + lane;
        float* myh2 = &h2b[half][0];

        #pragma unroll 1
        for (int p = 0; p < Tt / GRP; p++) {
            asm volatile("bar.sync 0, 128;" ::: "memory");
            #pragma unroll
            for (int s = 0; s < GRP; s++) {
                const int t = p * GRP + s;
                const u64* h1p = (const u64*)&ring[t & (RING - 1)][0];
                u64 aA = bA, aB = bB;
                #pragma unroll
                for (int kp = 0; kp < 10; kp++) {
                    u64 v = h1p[kp];
                    ffma2(aA, w1A[kp], v); ffma2(aB, w1B[kp], v);
                }
                #pragma unroll
                for (int kp = 0; kp < 10; kp++) {
                    u64 v = h2p[kp];
                    ffma2(aA, w2A[kp], v); ffma2(aB, w2B[kp], v);
                }
                float vA = fmaf(tanhfast(kA * hadd2(aA)), sA, dA);
                float vB = fmaf(tanhfast(0.5f * hadd2(aB)), 0.5f, 0.5f);
                gex[1][t & 1][half][lane] = make_float2(vA, vB);
                asm volatile("bar.sync %0, 64;" :: "r"(pbar) : "memory");
                float2 oth = gex[1][t & 1][half ^ 1][lane];
                float i_ = half ? oth.x : vA;
                float f_ = half ? oth.y : vB;
                float g_ = half ? vA : oth.x;
                float o_ = half ? vB : oth.y;
                c2 = fmaf(f_, c2, i_ * g_);
                float h2 = o_ * tanhfast(c2);
                if (lane < Hh) {
                    myh2[lane] = h2;
                    if (half == 0) *outp = h2;
                }
                outp += Bb * Hh;
                __syncwarp();
                const u64* rp2 = (const u64*)myh2;
                #pragma unroll
                for (int kp = 0; kp < 10; kp++) h2p[kp] = rp2[kp];
            }
        }
    }
}

extern "C" void kernel_launch(void* const* d_in, const int* in_sizes, int n_in,
                              void* d_out, int out_size) {
    lstm2_kernel<<<Bb, 128>>>(
        (const float*)d_in[0],
        (const float*)d_in[1], (const float*)d_in[2],
        (const float*)d_in[3], (const float*)d_in[4],
        (const float*)d_in[5], (const float*)d_in[6],
        (const float*)d_in[7], (const float*)d_in[8],
        (float*)d_out);
}

// round 9
// speedup vs baseline: 1.1890x; 1.1890x over previous
#include <cuda_runtime.h>

#define Tt 2048
#define Bb 512
#define Cc 8
#define Hh 20
#define GRP 4
#define RING 8

typedef unsigned long long u64;

__device__ __forceinline__ u64 pack2(float a, float b) {
    u64 r; asm("mov.b64 %0, {%1, %2};" : "=l"(r) : "f"(a), "f"(b)); return r;
}
__device__ __forceinline__ void unpack2(u64 v, float &a, float &b) {
    asm("mov.b64 {%0, %1}, %2;" : "=f"(a), "=f"(b) : "l"(v));
}
// packed dual-FMA: d.x += a.x*b.x ; d.y += a.y*b.y
__device__ __forceinline__ void ffma2(u64 &d, u64 a, u64 b) {
    asm("fma.rn.f32x2 %0, %1, %2, %0;" : "+l"(d) : "l"(a), "l"(b));
}
__device__ __forceinline__ u64 fadd2(u64 a, u64 b) {
    u64 r; asm("add.rn.f32x2 %0, %1, %2;" : "=l"(r) : "l"(a), "l"(b)); return r;
}
__device__ __forceinline__ float hadd2(u64 v) {
    float a, b; unpack2(v, a, b); return a + b;
}
__device__ __forceinline__ float tanhfast(float x) {
    float y; asm("tanh.approx.f32 %0, %1;" : "=f"(y) : "f"(x)); return y;
}
__device__ __forceinline__ float sigmfast(float x) {
    return fmaf(tanhfast(0.5f * x), 0.5f, 0.5f);
}

// R3 architecture (champion): 2 warps per batch, role 0 = layer-1 producer,
// role 1 = layer-2 consumer one GROUP (4 steps) behind via depth-8 smem ring,
// one named barrier per 4 steps, weights in registers, LDS.64 h broadcasts.
// R9 deltas: per-gate dual accumulator chains (late operand split 5+5),
// branchless x prefetch, strength-reduced output pointer.
__global__ void __launch_bounds__(256, 1) lstm2_kernel(
    const float* __restrict__ x,
    const float* __restrict__ Wih0, const float* __restrict__ Whh0,
    const float* __restrict__ bih0, const float* __restrict__ bhh0,
    const float* __restrict__ Wih1, const float* __restrict__ Whh1,
    const float* __restrict__ bih1, const float* __restrict__ bhh1,
    float* __restrict__ out)
{
    __shared__ __align__(16) float h1ring[4][RING][24];
    __shared__ __align__(16) float h2buf[4][24];

    const int tid   = threadIdx.x;
    const int w     = tid >> 5;
    const int lane  = tid & 31;
    const int pair  = w >> 1;
    // flip roles on pairs 2,3 so each SMSP hosts one L1 + one L2 warp
    const int role  = (w & 1) ^ ((w >> 2) & 1);
    const int batch = blockIdx.x * 4 + pair;
    const int barid = pair + 1;

    if (role == 0) {
        // ---------------- layer 1 (producer) ----------------
        u64 wx[4][4], wh[4][10], binit[4];
        if (lane < Hh) {
            #pragma unroll
            for (int g = 0; g < 4; g++) {
                const int row = g * Hh + lane;          // gate order i,f,g,o
                const float* rx = Wih0 + row * Cc;
                #pragma unroll
                for (int kp = 0; kp < 4; kp++)  wx[g][kp] = pack2(rx[2*kp], rx[2*kp+1]);
                const float* rh = Whh0 + row * Hh;
                #pragma unroll
                for (int kp = 0; kp < 10; kp++) wh[g][kp] = pack2(rh[2*kp], rh[2*kp+1]);
                binit[g] = pack2(bih0[row] + bhh0[row], 0.f);
            }
        }
        // x prefetch pipeline, depth 2 (uniform LDG.128 pairs, broadcast)
        const ulonglong2* xb = ((const ulonglong2*)x) + (size_t)batch * 2;
        ulonglong2 x0a = xb[0],    x0b = xb[1];        // t = 0
        ulonglong2 x1a = xb[1024], x1b = xb[1025];     // t = 1
        u64 hp[10];
        #pragma unroll
        for (int kp = 0; kp < 10; kp++) hp[kp] = 0ull;
        float c1 = 0.f;

        #pragma unroll 1
        for (int p = 0; p < Tt / GRP; p++) {
            #pragma unroll
            for (int s = 0; s < GRP; s++) {
                const int t = p * GRP + s;
                u64 xv0 = x0a.x, xv1 = x0a.y, xv2 = x0b.x, xv3 = x0b.y;
                x0a = x1a; x0b = x1b;
                {   // branchless prefetch of row min(t+2, Tt-1)
                    const int tpre = (t + 2 < Tt) ? (t + 2) : (Tt - 1);
                    const ulonglong2* xq = xb + (size_t)tpre * 1024;
                    x1a = xq[0]; x1b = xq[1];
                }
                // chain A: bias + x (early) + h k-pairs 0..4
                // chain B: h k-pairs 5..9 (late operand split 5+5)
                u64 a0 = binit[0], a1 = binit[1], a2 = binit[2], a3 = binit[3];
                u64 b0 = 0, b1 = 0, b2 = 0, b3 = 0;
                ffma2(a0, wx[0][0], xv0); ffma2(a1, wx[1][0], xv0);
                ffma2(a2, wx[2][0], xv0); ffma2(a3, wx[3][0], xv0);
                ffma2(a0, wx[0][1], xv1); ffma2(a1, wx[1][1], xv1);
                ffma2(a2, wx[2][1], xv1); ffma2(a3, wx[3][1], xv1);
                ffma2(a0, wx[0][2], xv2); ffma2(a1, wx[1][2], xv2);
                ffma2(a2, wx[2][2], xv2); ffma2(a3, wx[3][2], xv2);
                ffma2(a0, wx[0][3], xv3); ffma2(a1, wx[1][3], xv3);
                ffma2(a2, wx[2][3], xv3); ffma2(a3, wx[3][3], xv3);
                #pragma unroll
                for (int kp = 0; kp < 5; kp++) {
                    u64 v = hp[kp];
                    ffma2(a0, wh[0][kp], v); ffma2(a1, wh[1][kp], v);
                    ffma2(a2, wh[2][kp], v); ffma2(a3, wh[3][kp], v);
                }
                #pragma unroll
                for (int kp = 5; kp < 10; kp++) {
                    u64 v = hp[kp];
                    ffma2(b0, wh[0][kp], v); ffma2(b1, wh[1][kp], v);
                    ffma2(b2, wh[2][kp], v); ffma2(b3, wh[3][kp], v);
                }
                float ia = sigmfast(hadd2(fadd2(a0, b0)));
                float fa = sigmfast(hadd2(fadd2(a1, b1)));
                float ga = tanhfast(hadd2(fadd2(a2, b2)));
                float oa = sigmfast(hadd2(fadd2(a3, b3)));
                c1 = fmaf(fa, c1, ia * ga);
                float h1 = oa * tanhfast(c1);
                if (lane < Hh) h1ring[pair][t & (RING - 1)][lane] = h1;
                __syncwarp();
                // prefetch own broadcast pairs for next step (off critical path)
                const u64* rp = (const u64*)&h1ring[pair][t & (RING - 1)][0];
                #pragma unroll
                for (int kp = 0; kp < 10; kp++) hp[kp] = rp[kp];
            }
            asm volatile("bar.sync %0, 64;" :: "r"(barid) : "memory");
        }
    } else {
        // ---------------- layer 2 (consumer, one group behind) ----------------
        u64 w1[4][10], w2[4][10], binit[4];
        if (lane < Hh) {
            #pragma unroll
            for (int g = 0; g < 4; g++) {
                const int row = g * Hh + lane;
                const float* r1 = Wih1 + row * Hh;
                const float* r2 = Whh1 + row * Hh;
                #pragma unroll
                for (int kp = 0; kp < 10; kp++) {
                    w1[g][kp] = pack2(r1[2*kp], r1[2*kp+1]);
                    w2[g][kp] = pack2(r2[2*kp], r2[2*kp+1]);
                }
                binit[g] = pack2(bih1[row] + bhh1[row], 0.f);
            }
        }
        u64 h2p[10];
        #pragma unroll
        for (int kp = 0; kp < 10; kp++) h2p[kp] = 0ull;
        float c2 = 0.f;
        float* outp = out + (size_t)batch * Hh + lane;

        #pragma unroll 1
        for (int p = 0; p < Tt / GRP; p++) {
            asm volatile("bar.sync %0, 64;" :: "r"(barid) : "memory");
            u64 h1p[10];
            {
                const u64* rp = (const u64*)&h1ring[pair][(p * GRP) & (RING - 1)][0];
                #pragma unroll
                for (int kp = 0; kp < 10; kp++) h1p[kp] = rp[kp];
            }
            #pragma unroll
            for (int s = 0; s < GRP; s++) {
                const int t = p * GRP + s;
                // chain A: bias + h1 (early, prefetched) + h2 k-pairs 0..4
                // chain B: h2 k-pairs 5..9 (h2 is the late operand)
                u64 a0 = binit[0], a1 = binit[1], a2 = binit[2], a3 = binit[3];
                u64 b0 = 0, b1 = 0, b2 = 0, b3 = 0;
                #pragma unroll
                for (int kp = 0; kp < 10; kp++) {
                    u64 v = h1p[kp];
                    ffma2(a0, w1[0][kp], v); ffma2(a1, w1[1][kp], v);
                    ffma2(a2, w1[2][kp], v); ffma2(a3, w1[3][kp], v);
                }
                // prefetch next step's h1 (already in ring, written pre-barrier)
                if (s < GRP - 1) {
                    const u64* rp = (const u64*)&h1ring[pair][(t + 1) & (RING - 1)][0];
                    #pragma unroll
                    for (int kp = 0; kp < 10; kp++) h1p[kp] = rp[kp];
                }
                #pragma unroll
                for (int kp = 0; kp < 5; kp++) {
                    u64 v = h2p[kp];
                    ffma2(a0, w2[0][kp], v); ffma2(a1, w2[1][kp], v);
                    ffma2(a2, w2[2][kp], v); ffma2(a3, w2[3][kp], v);
                }
                #pragma unroll
                for (int kp = 5; kp < 10; kp++) {
                    u64 v = h2p[kp];
                    ffma2(b0, w2[0][kp], v); ffma2(b1, w2[1][kp], v);
                    ffma2(b2, w2[2][kp], v); ffma2(b3, w2[3][kp], v);
                }
                float ia = sigmfast(hadd2(fadd2(a0, b0)));
                float fa = sigmfast(hadd2(fadd2(a1, b1)));
                float ga = tanhfast(hadd2(fadd2(a2, b2)));
                float oa = sigmfast(hadd2(fadd2(a3, b3)));
                c2 = fmaf(fa, c2, ia * ga);
                float h2 = oa * tanhfast(c2);
                if (lane < Hh) {
                    *outp = h2;
                    h2buf[pair][lane] = h2;
                }
                outp += Bb * Hh;
                __syncwarp();
                const u64* rp2 = (const u64*)&h2buf[pair][0];
                #pragma unroll
                for (int kp = 0; kp < 10; kp++) h2p[kp] = rp2[kp];
            }
        }
    }
}

extern "C" void kernel_launch(void* const* d_in, const int* in_sizes, int n_in,
                              void* d_out, int out_size) {
    lstm2_kernel<<<Bb / 4, 256>>>(
        (const float*)d_in[0],
        (const float*)d_in[1], (const float*)d_in[2],
        (const float*)d_in[3], (const float*)d_in[4],
        (const float*)d_in[5], (const float*)d_in[6],
        (const float*)d_in[7], (const float*)d_in[8],
        (float*)d_out);
}

// round 10
// speedup vs baseline: 1.4075x; 1.1838x over previous
#include <cuda_runtime.h>

#define Tt 2048
#define Bb 512
#define Cc 8
#define Hh 20
#define GRP 4
#define RING 8

typedef unsigned long long u64;

__device__ __forceinline__ u64 pack2(float a, float b) {
    u64 r; asm("mov.b64 %0, {%1, %2};" : "=l"(r) : "f"(a), "f"(b)); return r;
}
__device__ __forceinline__ void unpack2(u64 v, float &a, float &b) {
    asm("mov.b64 {%0, %1}, %2;" : "=f"(a), "=f"(b) : "l"(v));
}
// packed dual-FMA: d.x += a.x*b.x ; d.y += a.y*b.y
__device__ __forceinline__ void ffma2(u64 &d, u64 a, u64 b) {
    asm("fma.rn.f32x2 %0, %1, %2, %0;" : "+l"(d) : "l"(a), "l"(b));
}
__device__ __forceinline__ float hadd2(u64 v) {
    float a, b; unpack2(v, a, b); return a + b;
}
__device__ __forceinline__ float tanhfast(float x) {
    float y; asm("tanh.approx.f32 %0, %1;" : "=f"(y) : "f"(x)); return y;
}
// sigmoid with the inner 0.5 pre-folded into weights/bias:
// sigmoid(z) = 0.5*tanh(0.5*z) + 0.5 ; acc already equals 0.5*z.
__device__ __forceinline__ float sigmfolded(float halfz) {
    return fmaf(tanhfast(halfz), 0.5f, 0.5f);
}

// Champion architecture (R3): 2 warps per batch element, role 0 = layer-1
// producer, role 1 = layer-2 consumer one GROUP (4 steps) behind, through a
// depth-8 smem ring. One named barrier per 4 steps. All weights in registers;
// h reads are LDS.64 broadcasts pipelined off the critical path.
// Sole delta vs champion: sigmoid-gate weights/biases pre-scaled by 0.5 at
// register-load time, deleting one dependent FMUL per sigmoid activation.
__global__ void __launch_bounds__(256, 1) lstm2_kernel(
    const float* __restrict__ x,
    const float* __restrict__ Wih0, const float* __restrict__ Whh0,
    const float* __restrict__ bih0, const float* __restrict__ bhh0,
    const float* __restrict__ Wih1, const float* __restrict__ Whh1,
    const float* __restrict__ bih1, const float* __restrict__ bhh1,
    float* __restrict__ out)
{
    __shared__ __align__(16) float h1ring[4][RING][24];
    __shared__ __align__(16) float h2buf[4][24];

    const int tid   = threadIdx.x;
    const int w     = tid >> 5;
    const int lane  = tid & 31;
    const int pair  = w >> 1;
    // flip roles on pairs 2,3 so each SMSP hosts one L1 + one L2 warp
    const int role  = (w & 1) ^ ((w >> 2) & 1);
    const int batch = blockIdx.x * 4 + pair;
    const int barid = pair + 1;

    if (role == 0) {
        // ---------------- layer 1 (producer) ----------------
        u64 wx[4][4], wh[4][10], binit[4];
        if (lane < Hh) {
            #pragma unroll
            for (int g = 0; g < 4; g++) {
                const float sc = (g == 2) ? 1.0f : 0.5f;   // fold sigmoid 0.5
                const int row = g * Hh + lane;              // gate order i,f,g,o
                const float* rx = Wih0 + row * Cc;
                #pragma unroll
                for (int kp = 0; kp < 4; kp++)
                    wx[g][kp] = pack2(sc * rx[2*kp], sc * rx[2*kp+1]);
                const float* rh = Whh0 + row * Hh;
                #pragma unroll
                for (int kp = 0; kp < 10; kp++)
                    wh[g][kp] = pack2(sc * rh[2*kp], sc * rh[2*kp+1]);
                binit[g] = pack2(sc * (bih0[row] + bhh0[row]), 0.f);
            }
        }
        // x prefetch pipeline, depth 2 (uniform LDG.128 pairs, broadcast)
        const ulonglong2* xb = ((const ulonglong2*)x) + (size_t)batch * 2;
        ulonglong2 x0a = xb[0],    x0b = xb[1];        // t = 0
        ulonglong2 x1a = xb[1024], x1b = xb[1025];     // t = 1
        u64 hp[10];
        #pragma unroll
        for (int kp = 0; kp < 10; kp++) hp[kp] = 0ull;
        float c1 = 0.f;

        #pragma unroll 1
        for (int p = 0; p < Tt / GRP; p++) {
            #pragma unroll
            for (int s = 0; s < GRP; s++) {
                const int t = p * GRP + s;
                u64 xv0 = x0a.x, xv1 = x0a.y, xv2 = x0b.x, xv3 = x0b.y;
                x0a = x1a; x0b = x1b;
                if (t + 2 < Tt) {                      // prefetch t+2
                    const ulonglong2* xq = xb + (size_t)(t + 2) * 1024;
                    x1a = xq[0]; x1b = xq[1];
                }
                u64 a0 = binit[0], a1 = binit[1], a2 = binit[2], a3 = binit[3];
                ffma2(a0, wx[0][0], xv0); ffma2(a1, wx[1][0], xv0);
                ffma2(a2, wx[2][0], xv0); ffma2(a3, wx[3][0], xv0);
                ffma2(a0, wx[0][1], xv1); ffma2(a1, wx[1][1], xv1);
                ffma2(a2, wx[2][1], xv1); ffma2(a3, wx[3][1], xv1);
                ffma2(a0, wx[0][2], xv2); ffma2(a1, wx[1][2], xv2);
                ffma2(a2, wx[2][2], xv2); ffma2(a3, wx[3][2], xv2);
                ffma2(a0, wx[0][3], xv3); ffma2(a1, wx[1][3], xv3);
                ffma2(a2, wx[2][3], xv3); ffma2(a3, wx[3][3], xv3);
                #pragma unroll
                for (int j = 0; j < 5; j++) {
                    u64 v0 = hp[2*j], v1 = hp[2*j+1];
                    ffma2(a0, wh[0][2*j],   v0); ffma2(a1, wh[1][2*j],   v0);
                    ffma2(a2, wh[2][2*j],   v0); ffma2(a3, wh[3][2*j],   v0);
                    ffma2(a0, wh[0][2*j+1], v1); ffma2(a1, wh[1][2*j+1], v1);
                    ffma2(a2, wh[2][2*j+1], v1); ffma2(a3, wh[3][2*j+1], v1);
                }
                float ia = sigmfolded(hadd2(a0));
                float fa = sigmfolded(hadd2(a1));
                float ga = tanhfast(hadd2(a2));
                float oa = sigmfolded(hadd2(a3));
                c1 = fmaf(fa, c1, ia * ga);
                float h1 = oa * tanhfast(c1);
                if (lane < Hh) h1ring[pair][t & (RING - 1)][lane] = h1;
                __syncwarp();
                // prefetch own broadcast pairs for next step (off critical path)
                const u64* rp = (const u64*)&h1ring[pair][t & (RING - 1)][0];
                #pragma unroll
                for (int kp = 0; kp < 10; kp++) hp[kp] = rp[kp];
            }
            asm volatile("bar.sync %0, 64;" :: "r"(barid) : "memory");
        }
    } else {
        // ---------------- layer 2 (consumer, one group behind) ----------------
        u64 w1[4][10], w2[4][10], binit[4];
        if (lane < Hh) {
            #pragma unroll
            for (int g = 0; g < 4; g++) {
                const float sc = (g == 2) ? 1.0f : 0.5f;   // fold sigmoid 0.5
                const int row = g * Hh + lane;
                const float* r1 = Wih1 + row * Hh;
                const float* r2 = Whh1 + row * Hh;
                #pragma unroll
                for (int kp = 0; kp < 10; kp++) {
                    w1[g][kp] = pack2(sc * r1[2*kp], sc * r1[2*kp+1]);
                    w2[g][kp] = pack2(sc * r2[2*kp], sc * r2[2*kp+1]);
                }
                binit[g] = pack2(sc * (bih1[row] + bhh1[row]), 0.f);
            }
        }
        u64 h2p[10];
        #pragma unroll
        for (int kp = 0; kp < 10; kp++) h2p[kp] = 0ull;
        float c2 = 0.f;

        #pragma unroll 1
        for (int p = 0; p < Tt / GRP; p++) {
            asm volatile("bar.sync %0, 64;" :: "r"(barid) : "memory");
            u64 h1p[10];
            {
                const u64* rp = (const u64*)&h1ring[pair][(p * GRP) & (RING - 1)][0];
                #pragma unroll
                for (int kp = 0; kp < 10; kp++) h1p[kp] = rp[kp];
            }
            #pragma unroll
            for (int s = 0; s < GRP; s++) {
                const int t = p * GRP + s;
                u64 a0 = binit[0], a1 = binit[1], a2 = binit[2], a3 = binit[3];
                #pragma unroll
                for (int j = 0; j < 5; j++) {
                    u64 v0 = h1p[2*j], v1 = h1p[2*j+1];
                    ffma2(a0, w1[0][2*j],   v0); ffma2(a1, w1[1][2*j],   v0);
                    ffma2(a2, w1[2][2*j],   v0); ffma2(a3, w1[3][2*j],   v0);
                    ffma2(a0, w1[0][2*j+1], v1); ffma2(a1, w1[1][2*j+1], v1);
                    ffma2(a2, w1[2][2*j+1], v1); ffma2(a3, w1[3][2*j+1], v1);
                }
                // prefetch next step's h1 (already in ring, written pre-barrier)
                if (s < GRP - 1) {
                    const u64* rp =
                        (const u64*)&h1ring[pair][(t + 1) & (RING - 1)][0];
                    #pragma unroll
                    for (int kp = 0; kp < 10; kp++) h1p[kp] = rp[kp];
                }
                #pragma unroll
                for (int j = 0; j < 5; j++) {
                    u64 v0 = h2p[2*j], v1 = h2p[2*j+1];
                    ffma2(a0, w2[0][2*j],   v0); ffma2(a1, w2[1][2*j],   v0);
                    ffma2(a2, w2[2][2*j],   v0); ffma2(a3, w2[3][2*j],   v0);
                    ffma2(a0, w2[0][2*j+1], v1); ffma2(a1, w2[1][2*j+1], v1);
                    ffma2(a2, w2[2][2*j+1], v1); ffma2(a3, w2[3][2*j+1], v1);
                }
                float ia = sigmfolded(hadd2(a0));
                float fa = sigmfolded(hadd2(a1));
                float ga = tanhfast(hadd2(a2));
                float oa = sigmfolded(hadd2(a3));
                c2 = fmaf(fa, c2, ia * ga);
                float h2 = oa * tanhfast(c2);
                if (lane < Hh) {
                    out[(size_t)t * Bb * Hh + batch * Hh + lane] = h2;
                    h2buf[pair][lane] = h2;
                }
                __syncwarp();
                const u64* rp2 = (const u64*)&h2buf[pair][0];
                #pragma unroll
                for (int kp = 0; kp < 10; kp++) h2p[kp] = rp2[kp];
            }
        }
    }
}

extern "C" void kernel_launch(void* const* d_in, const int* in_sizes, int n_in,
                              void* d_out, int out_size) {
    lstm2_kernel<<<Bb / 4, 256>>>(
        (const float*)d_in[0],
        (const float*)d_in[1], (const float*)d_in[2],
        (const float*)d_in[3], (const float*)d_in[4],
        (const float*)d_in[5], (const float*)d_in[6],
        (const float*)d_in[7], (const float*)d_in[8],
        (float*)d_out);
}